// round 1
// baseline (speedup 1.0000x reference)
#include <cuda_runtime.h>
#include <math.h>

#define B_ROWS 16384
#define HID    512
#define IN     256

// ---------------- scratch (static device globals; no allocations) ----------
__device__ float2 g_emb[(size_t)B_ROWS * HID];   // x @ W^T (re, im)
__device__ float2 g_d1brev[HID];                 // d1[brev(i)]
__device__ float2 g_d2brev[HID];                 // d2[brev(i)]
__device__ float2 g_d3[HID];
__device__ float2 g_v1[HID];
__device__ float2 g_v2[HID];
__device__ int    g_pperm[HID];                  // perm[brev(i)]
__device__ float2 g_tw[HID / 2];                 // exp(-2*pi*i*k/512), k<256

// ---------------- helpers ---------------------------------------------------
__device__ __forceinline__ float2 cmul(float2 a, float2 b) {
    return make_float2(fmaf(a.x, b.x, -a.y * b.y), fmaf(a.x, b.y, a.y * b.x));
}
__device__ __forceinline__ float2 cadd(float2 a, float2 b) {
    return make_float2(a.x + b.x, a.y + b.y);
}

// 256-thread (8-warp) complex block reduction
__device__ __forceinline__ float2 blockReduceC(float2 a, float2* red, int t) {
    #pragma unroll
    for (int o = 16; o; o >>= 1) {
        a.x += __shfl_xor_sync(0xffffffffu, a.x, o);
        a.y += __shfl_xor_sync(0xffffffffu, a.y, o);
    }
    if ((t & 31) == 0) red[t >> 5] = a;
    __syncthreads();
    float2 r = red[0];
    #pragma unroll
    for (int i = 1; i < 8; i++) { r.x += red[i].x; r.y += red[i].y; }
    return r;
}

// in-place radix-2 DIT FFT, N=512, input bit-reversed, 256 threads
// SIGN=-1: forward (exp(-2pi i nk/N)); SIGN=+1: inverse (no 1/N scaling here)
template <int SIGN>
__device__ __forceinline__ void fft512(float2* buf, int t) {
    #pragma unroll
    for (int s = 1; s <= 9; s++) {
        int half = 1 << (s - 1);
        int j    = t & (half - 1);
        int i0   = 2 * t - j;
        float2 w = g_tw[j << (9 - s)];
        if (SIGN > 0) w.y = -w.y;
        float2 u = buf[i0];
        float2 x = buf[i0 + half];
        float2 v = cmul(w, x);
        buf[i0]        = make_float2(u.x + v.x, u.y + v.y);
        buf[i0 + half] = make_float2(u.x - v.x, u.y - v.y);
        __syncthreads();
    }
}

// ---------------- prep: normalize v, diagonals, perm, twiddles --------------
__global__ void prep_kernel(const float* __restrict__ angles,
                            const float* __restrict__ rre,
                            const float* __restrict__ rim,
                            const int*   __restrict__ perm) {
    int t = threadIdx.x;  // 512 threads
    float a1 = rre[t],       b1 = rim[t];
    float a2 = rre[512 + t], b2 = rim[512 + t];
    float p = a1 * a1 + b1 * b1;
    float q = a2 * a2 + b2 * b2;
    #pragma unroll
    for (int o = 16; o; o >>= 1) {
        p += __shfl_xor_sync(0xffffffffu, p, o);
        q += __shfl_xor_sync(0xffffffffu, q, o);
    }
    __shared__ float sp[16], sq[16];
    __shared__ float fn1, fn2;
    int w = t >> 5, lane = t & 31;
    if (!lane) { sp[w] = p; sq[w] = q; }
    __syncthreads();
    if (t == 0) {
        float P = 0.f, Q = 0.f;
        for (int i = 0; i < 16; i++) { P += sp[i]; Q += sq[i]; }
        fn1 = 1.f / (sqrtf(P) + 1e-8f);
        fn2 = 1.f / (sqrtf(Q) + 1e-8f);
    }
    __syncthreads();
    g_v1[t] = make_float2(a1 * fn1, b1 * fn1);
    g_v2[t] = make_float2(a2 * fn2, b2 * fn2);

    int r = __brev((unsigned)t) >> 23;  // 9-bit reversal (involution)
    float s, c;
    sincosf(angles[t], &s, &c);          g_d1brev[r] = make_float2(c, s);
    sincosf(angles[512 + t], &s, &c);    g_d2brev[r] = make_float2(c, s);
    sincosf(angles[1024 + t], &s, &c);   g_d3[t]     = make_float2(c, s);
    g_pperm[r] = perm[t];

    if (t < 256) {
        double ang = -2.0 * 3.14159265358979323846 * (double)t / 512.0;
        g_tw[t] = make_float2((float)cos(ang), (float)sin(ang));
    }
}

// ---------------- GEMM: emb[b][h] = (x[b,:].Wre[h,:], x[b,:].Wim[h,:]) ------
// 64x64 tile, K chunks of 16, 256 threads, 4x4x2 accumulators per thread
__global__ void __launch_bounds__(256) gemm_kernel(const float* __restrict__ x,
                                                   const float* __restrict__ Wre,
                                                   const float* __restrict__ Wim) {
    __shared__ __align__(16) float As[16][64];
    __shared__ __align__(16) float Br[16][64];
    __shared__ __align__(16) float Bi[16][64];
    int tid = threadIdx.x;
    int bm  = blockIdx.y << 6;
    int bn  = blockIdx.x << 6;
    int tx  = tid & 15, ty = tid >> 4;
    int lrow = tid >> 2;
    int lk   = (tid & 3) << 2;
    float cre[4][4] = {{0.f}}, cim[4][4] = {{0.f}};

    for (int k0 = 0; k0 < IN; k0 += 16) {
        float4 a  = *(const float4*)(x   + (size_t)(bm + lrow) * IN + k0 + lk);
        float4 br = *(const float4*)(Wre + (size_t)(bn + lrow) * IN + k0 + lk);
        float4 bi = *(const float4*)(Wim + (size_t)(bn + lrow) * IN + k0 + lk);
        As[lk + 0][lrow] = a.x;  As[lk + 1][lrow] = a.y;
        As[lk + 2][lrow] = a.z;  As[lk + 3][lrow] = a.w;
        Br[lk + 0][lrow] = br.x; Br[lk + 1][lrow] = br.y;
        Br[lk + 2][lrow] = br.z; Br[lk + 3][lrow] = br.w;
        Bi[lk + 0][lrow] = bi.x; Bi[lk + 1][lrow] = bi.y;
        Bi[lk + 2][lrow] = bi.z; Bi[lk + 3][lrow] = bi.w;
        __syncthreads();
        #pragma unroll
        for (int kk = 0; kk < 16; kk++) {
            float4 av = *(const float4*)(&As[kk][ty << 2]);
            float4 bv = *(const float4*)(&Br[kk][tx << 2]);
            float4 cv = *(const float4*)(&Bi[kk][tx << 2]);
            float aa[4] = {av.x, av.y, av.z, av.w};
            float rr[4] = {bv.x, bv.y, bv.z, bv.w};
            float ii[4] = {cv.x, cv.y, cv.z, cv.w};
            #pragma unroll
            for (int i = 0; i < 4; i++)
                #pragma unroll
                for (int j = 0; j < 4; j++) {
                    cre[i][j] = fmaf(aa[i], rr[j], cre[i][j]);
                    cim[i][j] = fmaf(aa[i], ii[j], cim[i][j]);
                }
        }
        __syncthreads();
    }
    #pragma unroll
    for (int i = 0; i < 4; i++) {
        int m = bm + (ty << 2) + i;
        float2* op = g_emb + (size_t)m * HID + bn + (tx << 2);
        #pragma unroll
        for (int j = 0; j < 4; j++) op[j] = make_float2(cre[i][j], cim[i][j]);
    }
}

// ---------------- main per-row pipeline -------------------------------------
__global__ void __launch_bounds__(256) urnn_kernel(const float* __restrict__ hxr,
                                                   const float* __restrict__ hxi,
                                                   const float* __restrict__ beta,
                                                   float2* __restrict__ out) {
    __shared__ float2 A[512];
    __shared__ float2 Bf[512];
    __shared__ float2 red[8];
    int row = blockIdx.x;
    int t   = threadIdx.x;
    size_t base = (size_t)row * HID;

    // coalesced load of hx row
    A[t]       = make_float2(hxr[base + t],       hxi[base + t]);
    A[t + 256] = make_float2(hxr[base + t + 256], hxi[base + t + 256]);
    __syncthreads();

    // bit-reversed gather fused with D1:  Bf[i] = d1[brev(i)] * h[brev(i)]
    {
        int r0 = __brev((unsigned)t) >> 23;
        int r1 = __brev((unsigned)(t + 256)) >> 23;
        Bf[t]       = cmul(g_d1brev[t],       A[r0]);
        Bf[t + 256] = cmul(g_d1brev[t + 256], A[r1]);
    }
    __syncthreads();

    fft512<-1>(Bf, t);

    // Householder 1: h -= 2 (h.v1) conj(v1)
    float2 h0 = Bf[t], h1 = Bf[t + 256];
    float2 v0 = g_v1[t], v1 = g_v1[t + 256];
    float2 acc = cadd(cmul(h0, v0), cmul(h1, v1));
    float2 s = blockReduceC(acc, red, t);
    float2 m = make_float2(2.f * s.x, 2.f * s.y);
    float2 p0 = cmul(m, make_float2(v0.x, -v0.y));
    float2 p1 = cmul(m, make_float2(v1.x, -v1.y));
    Bf[t]       = make_float2(h0.x - p0.x, h0.y - p0.y);
    Bf[t + 256] = make_float2(h1.x - p1.x, h1.y - p1.y);
    __syncthreads();

    // A[i] = d2[brev(i)] * h[perm[brev(i)]]  (bit-reversed IFFT input)
    A[t]       = cmul(g_d2brev[t],       Bf[g_pperm[t]]);
    A[t + 256] = cmul(g_d2brev[t + 256], Bf[g_pperm[t + 256]]);
    __syncthreads();

    fft512<1>(A, t);

    const float inv = 1.f / 512.f;
    float2 z0 = A[t], z1 = A[t + 256];
    z0.x *= inv; z0.y *= inv; z1.x *= inv; z1.y *= inv;

    // Householder 2 (register-resident) + D3 + emb + ModReLU
    v0 = g_v2[t]; v1 = g_v2[t + 256];
    acc = cadd(cmul(z0, v0), cmul(z1, v1));
    s = blockReduceC(acc, red, t);
    m = make_float2(2.f * s.x, 2.f * s.y);

    #pragma unroll
    for (int half = 0; half < 2; half++) {
        int e = t + half * 256;
        float2 z = half ? z1 : z0;
        float2 v = half ? v1 : v0;
        float2 p = cmul(m, make_float2(v.x, -v.y));
        float2 h = make_float2(z.x - p.x, z.y - p.y);
        h = cmul(g_d3[e], h);
        float2 eb = g_emb[base + e];
        h.x += eb.x; h.y += eb.y;
        float d   = h.x * h.x + h.y * h.y;
        float mag = sqrtf(d);
        float r   = mag + beta[e];
        r = r > 0.f ? r : 0.f;
        float2 res;
        if (mag > 0.f) {
            float sc = r / mag;
            res = make_float2(sc * h.x, sc * h.y);
        } else {
            res = make_float2(r, 0.f);
        }
        out[base + e] = res;
    }
}

// ---------------- launch -----------------------------------------------------
extern "C" void kernel_launch(void* const* d_in, const int* in_sizes, int n_in,
                              void* d_out, int out_size) {
    const float* x      = (const float*)d_in[0];
    const float* hxr    = (const float*)d_in[1];
    const float* hxi    = (const float*)d_in[2];
    const float* angles = (const float*)d_in[3];
    const float* rre    = (const float*)d_in[4];
    const float* rim    = (const float*)d_in[5];
    const float* Wre    = (const float*)d_in[6];
    const float* Wim    = (const float*)d_in[7];
    const float* beta   = (const float*)d_in[8];
    const int*   perm   = (const int*)d_in[9];
    float2* out = (float2*)d_out;

    prep_kernel<<<1, 512>>>(angles, rre, rim, perm);
    dim3 gg(HID / 64, B_ROWS / 64);
    gemm_kernel<<<gg, 256>>>(x, Wre, Wim);
    urnn_kernel<<<B_ROWS, 256>>>(hxr, hxi, beta, out);
}

// round 4
// speedup vs baseline: 1.3261x; 1.3261x over previous
#include <cuda_runtime.h>
#include <cuda_bf16.h>
#include <cstdint>
#include <math.h>

typedef unsigned int u32;

#define B_ROWS 16384
#define HID    512
#define IN     256
#define KCAT   768   // [hi | hi | lo] for x, [hi | lo | hi] for W
#define NCAT   1024  // [Wre rows | Wim rows]

// ---------------- scratch (static device globals; no allocations) ----------
__device__ __nv_bfloat16 g_xcat[(size_t)B_ROWS * KCAT];  // 24 MB
__device__ __nv_bfloat16 g_wcat[(size_t)NCAT * KCAT];    // 1.5 MB
__device__ float  g_embP[(size_t)B_ROWS * NCAT];         // 64 MB planar: [re(512) | im(512)]
__device__ float2 g_d1brev[HID];
__device__ float2 g_d2brev[HID];
__device__ float2 g_d3[HID];
__device__ float2 g_v1[HID];
__device__ float2 g_v2[HID];
__device__ int    g_pperm[HID];
__device__ float2 g_tw[HID / 2];

// ---------------- helpers ---------------------------------------------------
__device__ __forceinline__ float2 cmul(float2 a, float2 b) {
    return make_float2(fmaf(a.x, b.x, -a.y * b.y), fmaf(a.x, b.y, a.y * b.x));
}
__device__ __forceinline__ float2 cadd(float2 a, float2 b) {
    return make_float2(a.x + b.x, a.y + b.y);
}

__device__ __forceinline__ float2 blockReduceC(float2 a, float2* red, int t) {
    #pragma unroll
    for (int o = 16; o; o >>= 1) {
        a.x += __shfl_xor_sync(0xffffffffu, a.x, o);
        a.y += __shfl_xor_sync(0xffffffffu, a.y, o);
    }
    if ((t & 31) == 0) red[t >> 5] = a;
    __syncthreads();
    float2 r = red[0];
    #pragma unroll
    for (int i = 1; i < 8; i++) { r.x += red[i].x; r.y += red[i].y; }
    return r;
}

template <int SIGN>
__device__ __forceinline__ void fft512(float2* buf, int t) {
    #pragma unroll
    for (int s = 1; s <= 9; s++) {
        int half = 1 << (s - 1);
        int j    = t & (half - 1);
        int i0   = 2 * t - j;
        float2 w = g_tw[j << (9 - s)];
        if (SIGN > 0) w.y = -w.y;
        float2 u = buf[i0];
        float2 x = buf[i0 + half];
        float2 v = cmul(w, x);
        buf[i0]        = make_float2(u.x + v.x, u.y + v.y);
        buf[i0 + half] = make_float2(u.x - v.x, u.y - v.y);
        __syncthreads();
    }
}

// ---------------- prep -------------------------------------------------------
__global__ void prep_kernel(const float* __restrict__ angles,
                            const float* __restrict__ rre,
                            const float* __restrict__ rim,
                            const int*   __restrict__ perm) {
    int t = threadIdx.x;  // 512 threads
    float a1 = rre[t],       b1 = rim[t];
    float a2 = rre[512 + t], b2 = rim[512 + t];
    float p = a1 * a1 + b1 * b1;
    float q = a2 * a2 + b2 * b2;
    #pragma unroll
    for (int o = 16; o; o >>= 1) {
        p += __shfl_xor_sync(0xffffffffu, p, o);
        q += __shfl_xor_sync(0xffffffffu, q, o);
    }
    __shared__ float sp[16], sq[16];
    __shared__ float fn1, fn2;
    int w = t >> 5, lane = t & 31;
    if (!lane) { sp[w] = p; sq[w] = q; }
    __syncthreads();
    if (t == 0) {
        float P = 0.f, Q = 0.f;
        for (int i = 0; i < 16; i++) { P += sp[i]; Q += sq[i]; }
        fn1 = 1.f / (sqrtf(P) + 1e-8f);
        fn2 = 1.f / (sqrtf(Q) + 1e-8f);
    }
    __syncthreads();
    g_v1[t] = make_float2(a1 * fn1, b1 * fn1);
    g_v2[t] = make_float2(a2 * fn2, b2 * fn2);

    int r = __brev((unsigned)t) >> 23;
    float s, c;
    sincosf(angles[t], &s, &c);          g_d1brev[r] = make_float2(c, s);
    sincosf(angles[512 + t], &s, &c);    g_d2brev[r] = make_float2(c, s);
    sincosf(angles[1024 + t], &s, &c);   g_d3[t]     = make_float2(c, s);
    g_pperm[r] = perm[t];

    if (t < 256) {
        double ang = -2.0 * 3.14159265358979323846 * (double)t / 512.0;
        g_tw[t] = make_float2((float)cos(ang), (float)sin(ang));
    }
}

// ---------------- split-bf16 conversion --------------------------------------
__global__ void convert_x_kernel(const float* __restrict__ x) {
    int idx = blockIdx.x * 256 + threadIdx.x;   // B_ROWS*IN threads
    float v = x[idx];
    __nv_bfloat16 hi = __float2bfloat16(v);
    __nv_bfloat16 lo = __float2bfloat16(v - __bfloat162float(hi));
    int row = idx >> 8, col = idx & 255;
    size_t b = (size_t)row * KCAT + col;
    g_xcat[b]       = hi;   // pairs with w_hi
    g_xcat[b + 256] = hi;   // pairs with w_lo
    g_xcat[b + 512] = lo;   // pairs with w_hi
}

__global__ void convert_w_kernel(const float* __restrict__ Wre,
                                 const float* __restrict__ Wim) {
    int idx = blockIdx.x * 256 + threadIdx.x;   // NCAT*IN threads
    int h = idx >> 8, col = idx & 255;
    float v = (h < 512) ? Wre[(size_t)h * 256 + col]
                        : Wim[(size_t)(h - 512) * 256 + col];
    __nv_bfloat16 hi = __float2bfloat16(v);
    __nv_bfloat16 lo = __float2bfloat16(v - __bfloat162float(hi));
    size_t b = (size_t)h * KCAT + col;
    g_wcat[b]       = hi;
    g_wcat[b + 256] = lo;
    g_wcat[b + 512] = hi;
}

// ---------------- tensor-core GEMM: embP = xcat @ wcat^T ---------------------
// M=16384, N=1024, K=768. CTA tile 128x128, BK=32, 8 warps (2M x 4N), warp 64x32.
// mma.sync.aligned.m16n8k16 bf16, fp32 accum. smem rows padded to 40 elems (80B).
// B stored [n][k] (k contiguous) == .col operand layout -> NON-trans ldmatrix,
// same lane addressing as A.
#define SROW 40

__device__ __forceinline__ void ldsm_x4(u32 addr, u32& r0, u32& r1,
                                        u32& r2, u32& r3) {
    asm volatile("ldmatrix.sync.aligned.m8n8.x4.shared.b16 {%0,%1,%2,%3}, [%4];"
                 : "=r"(r0), "=r"(r1), "=r"(r2), "=r"(r3) : "r"(addr));
}
__device__ __forceinline__ void mma16816(float* c, const u32* a,
                                         u32 b0, u32 b1) {
    asm volatile(
        "mma.sync.aligned.m16n8k16.row.col.f32.bf16.bf16.f32 "
        "{%0,%1,%2,%3}, {%4,%5,%6,%7}, {%8,%9}, {%0,%1,%2,%3};"
        : "+f"(c[0]), "+f"(c[1]), "+f"(c[2]), "+f"(c[3])
        : "r"(a[0]), "r"(a[1]), "r"(a[2]), "r"(a[3]), "r"(b0), "r"(b1));
}

__global__ void __launch_bounds__(256) mma_gemm_kernel() {
    __shared__ __align__(16) __nv_bfloat16 As[128 * SROW];
    __shared__ __align__(16) __nv_bfloat16 Bs[128 * SROW];

    int tid  = threadIdx.x;
    int warp = tid >> 5, lane = tid & 31;
    int bm = blockIdx.y << 7, bn = blockIdx.x << 7;
    int wm = (warp & 1) << 6, wn = (warp >> 1) << 5;

    // gmem load mapping: thread -> (row = tid/4 [+64], 8 elems at col (tid&3)*8)
    int lr = tid >> 2, lc = (tid & 3) << 3;
    const __nv_bfloat16* gA = g_xcat + (size_t)(bm + lr) * KCAT + lc;
    const __nv_bfloat16* gB = g_wcat + (size_t)(bn + lr) * KCAT + lc;

    __nv_bfloat16* sA0 = As + lr * SROW + lc;
    __nv_bfloat16* sA1 = As + (lr + 64) * SROW + lc;
    __nv_bfloat16* sB0 = Bs + lr * SROW + lc;
    __nv_bfloat16* sB1 = Bs + (lr + 64) * SROW + lc;

    // ldmatrix lane addressing (shared by A and B): lane&15 -> row within
    // 16-row group, lane>>4 -> k-halves (+0B / +16B)
    u32 aBase = (u32)__cvta_generic_to_shared(As);
    u32 bBase = (u32)__cvta_generic_to_shared(Bs);
    int frow  = lane & 15;
    int fbyte = (lane >> 4) << 4;
    u32 aAddr[4];
    #pragma unroll
    for (int i = 0; i < 4; i++)
        aAddr[i] = aBase + (u32)((wm + i * 16 + frow) * (SROW * 2) + fbyte);
    u32 bAddr[2];
    #pragma unroll
    for (int j = 0; j < 2; j++)
        bAddr[j] = bBase + (u32)((wn + j * 16 + frow) * (SROW * 2) + fbyte);

    float c[4][4][4];
    #pragma unroll
    for (int i = 0; i < 4; i++)
        #pragma unroll
        for (int j = 0; j < 4; j++)
            #pragma unroll
            for (int k = 0; k < 4; k++) c[i][j][k] = 0.f;

    int4 ra0 = *(const int4*)gA;
    int4 ra1 = *(const int4*)(gA + (size_t)64 * KCAT);
    int4 rb0 = *(const int4*)gB;
    int4 rb1 = *(const int4*)(gB + (size_t)64 * KCAT);

    #pragma unroll 1
    for (int iter = 0; iter < KCAT / 32; iter++) {
        *(int4*)sA0 = ra0;  *(int4*)sA1 = ra1;
        *(int4*)sB0 = rb0;  *(int4*)sB1 = rb1;
        __syncthreads();
        if (iter < KCAT / 32 - 1) {
            gA += 32; gB += 32;
            ra0 = *(const int4*)gA;
            ra1 = *(const int4*)(gA + (size_t)64 * KCAT);
            rb0 = *(const int4*)gB;
            rb1 = *(const int4*)(gB + (size_t)64 * KCAT);
        }
        #pragma unroll
        for (int kk = 0; kk < 2; kk++) {
            u32 a[4][4], b[2][4];
            #pragma unroll
            for (int i = 0; i < 4; i++)
                ldsm_x4(aAddr[i] + kk * 32, a[i][0], a[i][1], a[i][2], a[i][3]);
            #pragma unroll
            for (int j = 0; j < 2; j++)
                ldsm_x4(bAddr[j] + kk * 32, b[j][0], b[j][1], b[j][2], b[j][3]);
            // b[j][0] = n(16j..+7),k0-7  b[j][1] = n(16j+8..+15),k0-7
            // b[j][2] = n(16j..+7),k8-15 b[j][3] = n(16j+8..+15),k8-15
            #pragma unroll
            for (int i = 0; i < 4; i++)
                #pragma unroll
                for (int j = 0; j < 4; j++) {
                    int t = j >> 1, p = j & 1;
                    mma16816(c[i][j], a[i], b[t][p], b[t][p + 2]);
                }
        }
        __syncthreads();
    }

    // epilogue: c0=(g,2tg) c1=(g,2tg+1) c2=(g+8,2tg) c3=(g+8,2tg+1)
    int g = lane >> 2, tg = lane & 3;
    #pragma unroll
    for (int i = 0; i < 4; i++) {
        int r0 = bm + wm + i * 16 + g;
        #pragma unroll
        for (int j = 0; j < 4; j++) {
            int cc = bn + wn + j * 8 + tg * 2;
            *(float2*)(g_embP + (size_t)r0 * NCAT + cc)       = make_float2(c[i][j][0], c[i][j][1]);
            *(float2*)(g_embP + (size_t)(r0 + 8) * NCAT + cc) = make_float2(c[i][j][2], c[i][j][3]);
        }
    }
}

// ---------------- main per-row pipeline -------------------------------------
__global__ void __launch_bounds__(256) urnn_kernel(const float* __restrict__ hxr,
                                                   const float* __restrict__ hxi,
                                                   const float* __restrict__ beta,
                                                   float2* __restrict__ out) {
    __shared__ float2 A[512];
    __shared__ float2 Bf[512];
    __shared__ float2 red[8];
    int row = blockIdx.x;
    int t   = threadIdx.x;
    size_t base = (size_t)row * HID;

    A[t]       = make_float2(hxr[base + t],       hxi[base + t]);
    A[t + 256] = make_float2(hxr[base + t + 256], hxi[base + t + 256]);
    __syncthreads();

    {
        int r0 = __brev((unsigned)t) >> 23;
        int r1 = __brev((unsigned)(t + 256)) >> 23;
        Bf[t]       = cmul(g_d1brev[t],       A[r0]);
        Bf[t + 256] = cmul(g_d1brev[t + 256], A[r1]);
    }
    __syncthreads();

    fft512<-1>(Bf, t);

    float2 h0 = Bf[t], h1 = Bf[t + 256];
    float2 v0 = g_v1[t], v1 = g_v1[t + 256];
    float2 acc = cadd(cmul(h0, v0), cmul(h1, v1));
    float2 s = blockReduceC(acc, red, t);
    float2 m = make_float2(2.f * s.x, 2.f * s.y);
    float2 p0 = cmul(m, make_float2(v0.x, -v0.y));
    float2 p1 = cmul(m, make_float2(v1.x, -v1.y));
    Bf[t]       = make_float2(h0.x - p0.x, h0.y - p0.y);
    Bf[t + 256] = make_float2(h1.x - p1.x, h1.y - p1.y);
    __syncthreads();

    A[t]       = cmul(g_d2brev[t],       Bf[g_pperm[t]]);
    A[t + 256] = cmul(g_d2brev[t + 256], Bf[g_pperm[t + 256]]);
    __syncthreads();

    fft512<1>(A, t);

    const float inv = 1.f / 512.f;
    float2 z0 = A[t], z1 = A[t + 256];
    z0.x *= inv; z0.y *= inv; z1.x *= inv; z1.y *= inv;

    v0 = g_v2[t]; v1 = g_v2[t + 256];
    acc = cadd(cmul(z0, v0), cmul(z1, v1));
    s = blockReduceC(acc, red, t);
    m = make_float2(2.f * s.x, 2.f * s.y);

    const float* embRe = g_embP + (size_t)row * NCAT;
    const float* embIm = embRe + 512;

    #pragma unroll
    for (int half = 0; half < 2; half++) {
        int e = t + half * 256;
        float2 z = half ? z1 : z0;
        float2 v = half ? v1 : v0;
        float2 p = cmul(m, make_float2(v.x, -v.y));
        float2 h = make_float2(z.x - p.x, z.y - p.y);
        h = cmul(g_d3[e], h);
        h.x += embRe[e]; h.y += embIm[e];
        float d   = h.x * h.x + h.y * h.y;
        float mag = sqrtf(d);
        float r   = mag + beta[e];
        r = r > 0.f ? r : 0.f;
        float2 res;
        if (mag > 0.f) {
            float sc = r / mag;
            res = make_float2(sc * h.x, sc * h.y);
        } else {
            res = make_float2(r, 0.f);
        }
        out[base + e] = res;
    }
}

// ---------------- launch -----------------------------------------------------
extern "C" void kernel_launch(void* const* d_in, const int* in_sizes, int n_in,
                              void* d_out, int out_size) {
    const float* x      = (const float*)d_in[0];
    const float* hxr    = (const float*)d_in[1];
    const float* hxi    = (const float*)d_in[2];
    const float* angles = (const float*)d_in[3];
    const float* rre    = (const float*)d_in[4];
    const float* rim    = (const float*)d_in[5];
    const float* Wre    = (const float*)d_in[6];
    const float* Wim    = (const float*)d_in[7];
    const float* beta   = (const float*)d_in[8];
    const int*   perm   = (const int*)d_in[9];
    float2* out = (float2*)d_out;

    prep_kernel<<<1, 512>>>(angles, rre, rim, perm);
    convert_x_kernel<<<B_ROWS * IN / 256, 256>>>(x);
    convert_w_kernel<<<NCAT * IN / 256, 256>>>(Wre, Wim);
    dim3 gg(NCAT / 128, B_ROWS / 128);
    mma_gemm_kernel<<<gg, 256>>>();
    urnn_kernel<<<B_ROWS, 256>>>(hxr, hxi, beta, out);
}

// round 5
// speedup vs baseline: 2.0995x; 1.5831x over previous
#include <cuda_runtime.h>
#include <cuda_bf16.h>
#include <cstdint>
#include <math.h>

typedef unsigned int u32;

#define B_ROWS 16384
#define HID    512
#define IN     256
#define KCAT   768
#define NCAT   1024

#define PAD(i) ((i) + ((i) >> 3))

// ---------------- scratch ---------------------------------------------------
__device__ __nv_bfloat16 g_xcat[(size_t)B_ROWS * KCAT];
__device__ __nv_bfloat16 g_wcat[(size_t)NCAT * KCAT];
__device__ float  g_embP[(size_t)B_ROWS * NCAT];  // planar per row: [re(512) | im(512)]
__device__ float2 g_d1r8[HID];   // d1[rev8(i)]
__device__ float2 g_d2r8[HID];   // d2[rev8(i)]
__device__ float2 g_d3[HID];
__device__ float2 g_v1[HID];
__device__ float2 g_v2[HID];
__device__ int    g_pp8[HID];    // PAD(perm[rev8(i)])
__device__ float2 g_tw[64];      // exp(-2*pi*i*k/512), k<64

// ---------------- helpers ---------------------------------------------------
__device__ __forceinline__ float2 cmul(float2 a, float2 b) {
    return make_float2(fmaf(a.x, b.x, -a.y * b.y), fmaf(a.x, b.y, a.y * b.x));
}
__device__ __forceinline__ float2 cadd(float2 a, float2 b) {
    return make_float2(a.x + b.x, a.y + b.y);
}
__device__ __forceinline__ float2 csub(float2 a, float2 b) {
    return make_float2(a.x - b.x, a.y - b.y);
}

// 8-point DFT, SIGN=-1 forward (W=e^{-2pi i/8}), SIGN=+1 inverse
template <int SIGN>
__device__ __forceinline__ void dft8(float2 x[8]) {
    const float S = 0.70710678118654752440f;
    float2 a0 = cadd(x[0], x[4]), b0 = csub(x[0], x[4]);
    float2 a1 = cadd(x[1], x[5]), b1 = csub(x[1], x[5]);
    float2 a2 = cadd(x[2], x[6]), b2 = csub(x[2], x[6]);
    float2 a3 = cadd(x[3], x[7]), b3 = csub(x[3], x[7]);
    b1 = cmul(b1, make_float2(S, SIGN * S));
    b2 = (SIGN < 0) ? make_float2(b2.y, -b2.x) : make_float2(-b2.y, b2.x);
    b3 = cmul(b3, make_float2(-S, SIGN * S));
    float2 c0 = cadd(a0, a2), c1 = csub(a0, a2);
    float2 c2 = cadd(a1, a3), c3 = csub(a1, a3);
    c3 = (SIGN < 0) ? make_float2(c3.y, -c3.x) : make_float2(-c3.y, c3.x);
    x[0] = cadd(c0, c2); x[4] = csub(c0, c2);
    x[2] = cadd(c1, c3); x[6] = csub(c1, c3);
    float2 d0 = cadd(b0, b2), d1 = csub(b0, b2);
    float2 d2 = cadd(b1, b3), d3 = csub(b1, b3);
    d3 = (SIGN < 0) ? make_float2(d3.y, -d3.x) : make_float2(-d3.y, d3.x);
    x[1] = cadd(d0, d2); x[5] = csub(d0, d2);
    x[3] = cadd(d1, d3); x[7] = csub(d1, d3);
}

// stage 1 of radix-8 DIT (half=8), in place on padded buffer
template <int SIGN>
__device__ __forceinline__ void fft_stage1(float2* b, int t) {
    int j = t & 7, g = t >> 3;
    int base = (g << 6) + j;
    float2 x[8];
    #pragma unroll
    for (int k = 0; k < 8; k++) x[k] = b[PAD(base + (k << 3))];
    float2 w1 = g_tw[j << 3];
    if (SIGN > 0) w1.y = -w1.y;
    float2 w = w1;
    #pragma unroll
    for (int k = 1; k < 8; k++) { x[k] = cmul(x[k], w); w = cmul(w, w1); }
    dft8<SIGN>(x);
    #pragma unroll
    for (int k = 0; k < 8; k++) b[PAD(base + (k << 3))] = x[k];
}

// ---------------- prep -------------------------------------------------------
__global__ void prep_kernel(const float* __restrict__ angles,
                            const float* __restrict__ rre,
                            const float* __restrict__ rim,
                            const int*   __restrict__ perm) {
    int t = threadIdx.x;  // 512 threads
    float a1 = rre[t],       b1 = rim[t];
    float a2 = rre[512 + t], b2 = rim[512 + t];
    float p = a1 * a1 + b1 * b1;
    float q = a2 * a2 + b2 * b2;
    #pragma unroll
    for (int o = 16; o; o >>= 1) {
        p += __shfl_xor_sync(0xffffffffu, p, o);
        q += __shfl_xor_sync(0xffffffffu, q, o);
    }
    __shared__ float sp[16], sq[16];
    __shared__ float fn1, fn2;
    int w = t >> 5, lane = t & 31;
    if (!lane) { sp[w] = p; sq[w] = q; }
    __syncthreads();
    if (t == 0) {
        float P = 0.f, Q = 0.f;
        for (int i = 0; i < 16; i++) { P += sp[i]; Q += sq[i]; }
        fn1 = 1.f / (sqrtf(P) + 1e-8f);
        fn2 = 1.f / (sqrtf(Q) + 1e-8f);
    }
    __syncthreads();
    g_v1[t] = make_float2(a1 * fn1, b1 * fn1);
    g_v2[t] = make_float2(a2 * fn2, b2 * fn2);

    // base-8 digit reversal of t (3 digits): involution
    int r8 = ((t & 7) << 6) | (t & 56) | (t >> 6);
    float s, c;
    sincosf(angles[t], &s, &c);          g_d1r8[r8] = make_float2(c, s);
    sincosf(angles[512 + t], &s, &c);    g_d2r8[r8] = make_float2(c, s);
    sincosf(angles[1024 + t], &s, &c);   g_d3[t]    = make_float2(c, s);
    g_pp8[r8] = PAD(perm[t]);

    if (t < 64) {
        double ang = -2.0 * 3.14159265358979323846 * (double)t / 512.0;
        g_tw[t] = make_float2((float)cos(ang), (float)sin(ang));
    }
}

// ---------------- split-bf16 conversion --------------------------------------
__global__ void convert_x_kernel(const float* __restrict__ x) {
    int idx = blockIdx.x * 256 + threadIdx.x;
    float v = x[idx];
    __nv_bfloat16 hi = __float2bfloat16(v);
    __nv_bfloat16 lo = __float2bfloat16(v - __bfloat162float(hi));
    int row = idx >> 8, col = idx & 255;
    size_t b = (size_t)row * KCAT + col;
    g_xcat[b]       = hi;
    g_xcat[b + 256] = hi;
    g_xcat[b + 512] = lo;
}

__global__ void convert_w_kernel(const float* __restrict__ Wre,
                                 const float* __restrict__ Wim) {
    int idx = blockIdx.x * 256 + threadIdx.x;
    int h = idx >> 8, col = idx & 255;
    float v = (h < 512) ? Wre[(size_t)h * 256 + col]
                        : Wim[(size_t)(h - 512) * 256 + col];
    __nv_bfloat16 hi = __float2bfloat16(v);
    __nv_bfloat16 lo = __float2bfloat16(v - __bfloat162float(hi));
    size_t b = (size_t)h * KCAT + col;
    g_wcat[b]       = hi;
    g_wcat[b + 256] = lo;
    g_wcat[b + 512] = hi;
}

// ---------------- tensor-core GEMM (unchanged from R4) -----------------------
#define SROW 40

__device__ __forceinline__ void ldsm_x4(u32 addr, u32& r0, u32& r1,
                                        u32& r2, u32& r3) {
    asm volatile("ldmatrix.sync.aligned.m8n8.x4.shared.b16 {%0,%1,%2,%3}, [%4];"
                 : "=r"(r0), "=r"(r1), "=r"(r2), "=r"(r3) : "r"(addr));
}
__device__ __forceinline__ void mma16816(float* c, const u32* a,
                                         u32 b0, u32 b1) {
    asm volatile(
        "mma.sync.aligned.m16n8k16.row.col.f32.bf16.bf16.f32 "
        "{%0,%1,%2,%3}, {%4,%5,%6,%7}, {%8,%9}, {%0,%1,%2,%3};"
        : "+f"(c[0]), "+f"(c[1]), "+f"(c[2]), "+f"(c[3])
        : "r"(a[0]), "r"(a[1]), "r"(a[2]), "r"(a[3]), "r"(b0), "r"(b1));
}

__global__ void __launch_bounds__(256) mma_gemm_kernel() {
    __shared__ __align__(16) __nv_bfloat16 As[128 * SROW];
    __shared__ __align__(16) __nv_bfloat16 Bs[128 * SROW];

    int tid  = threadIdx.x;
    int warp = tid >> 5, lane = tid & 31;
    int bm = blockIdx.y << 7, bn = blockIdx.x << 7;
    int wm = (warp & 1) << 6, wn = (warp >> 1) << 5;

    int lr = tid >> 2, lc = (tid & 3) << 3;
    const __nv_bfloat16* gA = g_xcat + (size_t)(bm + lr) * KCAT + lc;
    const __nv_bfloat16* gB = g_wcat + (size_t)(bn + lr) * KCAT + lc;

    __nv_bfloat16* sA0 = As + lr * SROW + lc;
    __nv_bfloat16* sA1 = As + (lr + 64) * SROW + lc;
    __nv_bfloat16* sB0 = Bs + lr * SROW + lc;
    __nv_bfloat16* sB1 = Bs + (lr + 64) * SROW + lc;

    u32 aBase = (u32)__cvta_generic_to_shared(As);
    u32 bBase = (u32)__cvta_generic_to_shared(Bs);
    int frow  = lane & 15;
    int fbyte = (lane >> 4) << 4;
    u32 aAddr[4];
    #pragma unroll
    for (int i = 0; i < 4; i++)
        aAddr[i] = aBase + (u32)((wm + i * 16 + frow) * (SROW * 2) + fbyte);
    u32 bAddr[2];
    #pragma unroll
    for (int j = 0; j < 2; j++)
        bAddr[j] = bBase + (u32)((wn + j * 16 + frow) * (SROW * 2) + fbyte);

    float c[4][4][4];
    #pragma unroll
    for (int i = 0; i < 4; i++)
        #pragma unroll
        for (int j = 0; j < 4; j++)
            #pragma unroll
            for (int k = 0; k < 4; k++) c[i][j][k] = 0.f;

    int4 ra0 = *(const int4*)gA;
    int4 ra1 = *(const int4*)(gA + (size_t)64 * KCAT);
    int4 rb0 = *(const int4*)gB;
    int4 rb1 = *(const int4*)(gB + (size_t)64 * KCAT);

    #pragma unroll 1
    for (int iter = 0; iter < KCAT / 32; iter++) {
        *(int4*)sA0 = ra0;  *(int4*)sA1 = ra1;
        *(int4*)sB0 = rb0;  *(int4*)sB1 = rb1;
        __syncthreads();
        if (iter < KCAT / 32 - 1) {
            gA += 32; gB += 32;
            ra0 = *(const int4*)gA;
            ra1 = *(const int4*)(gA + (size_t)64 * KCAT);
            rb0 = *(const int4*)gB;
            rb1 = *(const int4*)(gB + (size_t)64 * KCAT);
        }
        #pragma unroll
        for (int kk = 0; kk < 2; kk++) {
            u32 a[4][4], b[2][4];
            #pragma unroll
            for (int i = 0; i < 4; i++)
                ldsm_x4(aAddr[i] + kk * 32, a[i][0], a[i][1], a[i][2], a[i][3]);
            #pragma unroll
            for (int j = 0; j < 2; j++)
                ldsm_x4(bAddr[j] + kk * 32, b[j][0], b[j][1], b[j][2], b[j][3]);
            #pragma unroll
            for (int i = 0; i < 4; i++)
                #pragma unroll
                for (int j = 0; j < 4; j++) {
                    int t = j >> 1, p = j & 1;
                    mma16816(c[i][j], a[i], b[t][p], b[t][p + 2]);
                }
        }
        __syncthreads();
    }

    int g = lane >> 2, tg = lane & 3;
    #pragma unroll
    for (int i = 0; i < 4; i++) {
        int r0 = bm + wm + i * 16 + g;
        #pragma unroll
        for (int j = 0; j < 4; j++) {
            int cc = bn + wn + j * 8 + tg * 2;
            *(float2*)(g_embP + (size_t)r0 * NCAT + cc)       = make_float2(c[i][j][0], c[i][j][1]);
            *(float2*)(g_embP + (size_t)(r0 + 8) * NCAT + cc) = make_float2(c[i][j][2], c[i][j][3]);
        }
    }
}

// ---------------- main per-row pipeline: 4 rows/block, radix-8 FFT -----------
__global__ void __launch_bounds__(256) urnn_kernel(const float* __restrict__ hxr,
                                                   const float* __restrict__ hxi,
                                                   const float* __restrict__ beta,
                                                   float2* __restrict__ out) {
    __shared__ float2 buf[4][576];   // 512 + pad
    __shared__ float2 sred[8];

    int tid = threadIdx.x;
    int sub = tid >> 6;            // row within block (0..3)
    int t   = tid & 63;            // lane within row
    int warp = tid >> 5;
    int row = (blockIdx.x << 2) + sub;
    size_t base  = (size_t)row * HID;
    size_t gbase = (size_t)(blockIdx.x << 2) * HID;

    // coalesced load of 4 rows into natural-order padded smem
    #pragma unroll
    for (int n = 0; n < 8; n++) {
        int l = tid + (n << 8);          // 0..2047
        int r = l >> 9, i = l & 511;
        buf[r][PAD(i)] = make_float2(hxr[gbase + l], hxi[gbase + l]);
    }
    __syncthreads();

    float2* b = buf[sub];
    float2 x[8];

    // ===== forward FFT =====
    // stage 0 fused with digit-reversal gather + D1 (twiddles = 1)
    #pragma unroll
    for (int k = 0; k < 8; k++) {
        int i  = (t << 3) + k;
        int r8 = (k << 6) + ((t & 7) << 3) + (t >> 3);   // rev8(i)
        x[k] = cmul(g_d1r8[i], b[PAD(r8)]);
    }
    dft8<-1>(x);
    __syncthreads();                      // all gathers done before overwrite
    #pragma unroll
    for (int k = 0; k < 8; k++) b[PAD((t << 3) + k)] = x[k];
    __syncthreads();

    fft_stage1<-1>(b, t);
    __syncthreads();

    // stage 2 (half=64): keep outputs in registers (natural positions t+64k)
    #pragma unroll
    for (int k = 0; k < 8; k++) x[k] = b[PAD(t + (k << 6))];
    {
        float2 w1 = g_tw[t];
        float2 w = w1;
        #pragma unroll
        for (int k = 1; k < 8; k++) { x[k] = cmul(x[k], w); w = cmul(w, w1); }
    }
    dft8<-1>(x);

    // Householder 1: s = sum h*v1 (per row, 64 threads = 2 warps)
    float2 v[8];
    float2 acc = make_float2(0.f, 0.f);
    #pragma unroll
    for (int k = 0; k < 8; k++) {
        v[k] = g_v1[t + (k << 6)];
        acc = cadd(acc, cmul(x[k], v[k]));
    }
    #pragma unroll
    for (int o = 16; o; o >>= 1) {
        acc.x += __shfl_xor_sync(0xffffffffu, acc.x, o);
        acc.y += __shfl_xor_sync(0xffffffffu, acc.y, o);
    }
    if ((tid & 31) == 0) sred[warp] = acc;
    __syncthreads();
    {
        float2 s = cadd(sred[sub << 1], sred[(sub << 1) | 1]);
        float2 m = make_float2(2.f * s.x, 2.f * s.y);
        #pragma unroll
        for (int k = 0; k < 8; k++)
            x[k] = csub(x[k], cmul(m, make_float2(v[k].x, -v[k].y)));
    }
    __syncthreads();                      // sred consumed by all before reuse
    // store hh natural order
    #pragma unroll
    for (int k = 0; k < 8; k++) b[PAD(t + (k << 6))] = x[k];
    __syncthreads();

    // ===== inverse FFT =====
    // stage 0 fused with perm∘rev8 gather + D2
    #pragma unroll
    for (int k = 0; k < 8; k++) {
        int i = (t << 3) + k;
        x[k] = cmul(g_d2r8[i], b[g_pp8[i]]);
    }
    dft8<1>(x);
    __syncthreads();
    #pragma unroll
    for (int k = 0; k < 8; k++) b[PAD((t << 3) + k)] = x[k];
    __syncthreads();

    fft_stage1<1>(b, t);
    __syncthreads();

    #pragma unroll
    for (int k = 0; k < 8; k++) x[k] = b[PAD(t + (k << 6))];
    {
        float2 w1 = g_tw[t]; w1.y = -w1.y;
        float2 w = w1;
        #pragma unroll
        for (int k = 1; k < 8; k++) { x[k] = cmul(x[k], w); w = cmul(w, w1); }
    }
    dft8<1>(x);

    const float inv = 1.f / 512.f;
    #pragma unroll
    for (int k = 0; k < 8; k++) { x[k].x *= inv; x[k].y *= inv; }

    // Householder 2
    acc = make_float2(0.f, 0.f);
    #pragma unroll
    for (int k = 0; k < 8; k++) {
        v[k] = g_v2[t + (k << 6)];
        acc = cadd(acc, cmul(x[k], v[k]));
    }
    #pragma unroll
    for (int o = 16; o; o >>= 1) {
        acc.x += __shfl_xor_sync(0xffffffffu, acc.x, o);
        acc.y += __shfl_xor_sync(0xffffffffu, acc.y, o);
    }
    if ((tid & 31) == 0) sred[warp] = acc;
    __syncthreads();
    float2 s2 = cadd(sred[sub << 1], sred[(sub << 1) | 1]);
    float2 m2 = make_float2(2.f * s2.x, 2.f * s2.y);

    const float* embRe = g_embP + (size_t)row * NCAT;
    const float* embIm = embRe + 512;

    #pragma unroll
    for (int k = 0; k < 8; k++) {
        int e = t + (k << 6);
        float2 h = csub(x[k], cmul(m2, make_float2(v[k].x, -v[k].y)));
        h = cmul(g_d3[e], h);
        h.x += embRe[e]; h.y += embIm[e];
        float mag = sqrtf(h.x * h.x + h.y * h.y);
        float r = mag + beta[e];
        r = r > 0.f ? r : 0.f;
        float2 res;
        if (mag > 0.f) {
            float sc = r / mag;
            res = make_float2(sc * h.x, sc * h.y);
        } else {
            res = make_float2(r, 0.f);
        }
        out[base + e] = res;
    }
}

// ---------------- launch -----------------------------------------------------
extern "C" void kernel_launch(void* const* d_in, const int* in_sizes, int n_in,
                              void* d_out, int out_size) {
    const float* x      = (const float*)d_in[0];
    const float* hxr    = (const float*)d_in[1];
    const float* hxi    = (const float*)d_in[2];
    const float* angles = (const float*)d_in[3];
    const float* rre    = (const float*)d_in[4];
    const float* rim    = (const float*)d_in[5];
    const float* Wre    = (const float*)d_in[6];
    const float* Wim    = (const float*)d_in[7];
    const float* beta   = (const float*)d_in[8];
    const int*   perm   = (const int*)d_in[9];
    float2* out = (float2*)d_out;

    prep_kernel<<<1, 512>>>(angles, rre, rim, perm);
    convert_x_kernel<<<B_ROWS * IN / 256, 256>>>(x);
    convert_w_kernel<<<NCAT * IN / 256, 256>>>(Wre, Wim);
    dim3 gg(NCAT / 128, B_ROWS / 128);
    mma_gemm_kernel<<<gg, 256>>>();
    urnn_kernel<<<B_ROWS / 4, 256>>>(hxr, hxi, beta, out);
}

// round 6
// speedup vs baseline: 2.1354x; 1.0171x over previous
#include <cuda_runtime.h>
#include <cuda_bf16.h>
#include <cstdint>
#include <math.h>

typedef unsigned int u32;

#define B_ROWS 16384
#define HID    512
#define IN     256
#define KCAT   768
#define NCAT   1024

#define PAD(i) ((i) + ((i) >> 3))

// ---------------- scratch ---------------------------------------------------
__device__ __nv_bfloat16 g_xcat[(size_t)B_ROWS * KCAT];
__device__ __nv_bfloat16 g_wcat[(size_t)NCAT * KCAT];
__device__ float  g_embP[(size_t)B_ROWS * NCAT];  // planar per row: [re(512) | im(512)]
__device__ float2 g_d1r8[HID];   // d1[rev8(i)]
__device__ float2 g_d2r8[HID];   // d2[rev8(i)]
__device__ float2 g_d3[HID];
__device__ float2 g_v1[HID];
__device__ float2 g_v2[HID];
__device__ int    g_pp8[HID];    // PAD(perm[rev8(i)])
__device__ float2 g_tw[64];      // exp(-2*pi*i*k/512), k<64

// ---------------- helpers ---------------------------------------------------
__device__ __forceinline__ float2 cmul(float2 a, float2 b) {
    return make_float2(fmaf(a.x, b.x, -a.y * b.y), fmaf(a.x, b.y, a.y * b.x));
}
__device__ __forceinline__ float2 cadd(float2 a, float2 b) {
    return make_float2(a.x + b.x, a.y + b.y);
}
__device__ __forceinline__ float2 csub(float2 a, float2 b) {
    return make_float2(a.x - b.x, a.y - b.y);
}

// 8-point DFT, SIGN=-1 forward, SIGN=+1 inverse
template <int SIGN>
__device__ __forceinline__ void dft8(float2 x[8]) {
    const float S = 0.70710678118654752440f;
    float2 a0 = cadd(x[0], x[4]), b0 = csub(x[0], x[4]);
    float2 a1 = cadd(x[1], x[5]), b1 = csub(x[1], x[5]);
    float2 a2 = cadd(x[2], x[6]), b2 = csub(x[2], x[6]);
    float2 a3 = cadd(x[3], x[7]), b3 = csub(x[3], x[7]);
    b1 = cmul(b1, make_float2(S, SIGN * S));
    b2 = (SIGN < 0) ? make_float2(b2.y, -b2.x) : make_float2(-b2.y, b2.x);
    b3 = cmul(b3, make_float2(-S, SIGN * S));
    float2 c0 = cadd(a0, a2), c1 = csub(a0, a2);
    float2 c2 = cadd(a1, a3), c3 = csub(a1, a3);
    c3 = (SIGN < 0) ? make_float2(c3.y, -c3.x) : make_float2(-c3.y, c3.x);
    x[0] = cadd(c0, c2); x[4] = csub(c0, c2);
    x[2] = cadd(c1, c3); x[6] = csub(c1, c3);
    float2 d0 = cadd(b0, b2), d1 = csub(b0, b2);
    float2 d2 = cadd(b1, b3), d3 = csub(b1, b3);
    d3 = (SIGN < 0) ? make_float2(d3.y, -d3.x) : make_float2(-d3.y, d3.x);
    x[1] = cadd(d0, d2); x[5] = csub(d0, d2);
    x[3] = cadd(d1, d3); x[7] = csub(d1, d3);
}

template <int SIGN>
__device__ __forceinline__ void fft_stage1(float2* b, int t) {
    int j = t & 7, g = t >> 3;
    int base = (g << 6) + j;
    float2 x[8];
    #pragma unroll
    for (int k = 0; k < 8; k++) x[k] = b[PAD(base + (k << 3))];
    float2 w1 = g_tw[j << 3];
    if (SIGN > 0) w1.y = -w1.y;
    float2 w = w1;
    #pragma unroll
    for (int k = 1; k < 8; k++) { x[k] = cmul(x[k], w); w = cmul(w, w1); }
    dft8<SIGN>(x);
    #pragma unroll
    for (int k = 0; k < 8; k++) b[PAD(base + (k << 3))] = x[k];
}

// ---------------- prep -------------------------------------------------------
__global__ void prep_kernel(const float* __restrict__ angles,
                            const float* __restrict__ rre,
                            const float* __restrict__ rim,
                            const int*   __restrict__ perm) {
    int t = threadIdx.x;  // 512 threads
    float a1 = rre[t],       b1 = rim[t];
    float a2 = rre[512 + t], b2 = rim[512 + t];
    float p = a1 * a1 + b1 * b1;
    float q = a2 * a2 + b2 * b2;
    #pragma unroll
    for (int o = 16; o; o >>= 1) {
        p += __shfl_xor_sync(0xffffffffu, p, o);
        q += __shfl_xor_sync(0xffffffffu, q, o);
    }
    __shared__ float sp[16], sq[16];
    __shared__ float fn1, fn2;
    int w = t >> 5, lane = t & 31;
    if (!lane) { sp[w] = p; sq[w] = q; }
    __syncthreads();
    if (t == 0) {
        float P = 0.f, Q = 0.f;
        for (int i = 0; i < 16; i++) { P += sp[i]; Q += sq[i]; }
        fn1 = 1.f / (sqrtf(P) + 1e-8f);
        fn2 = 1.f / (sqrtf(Q) + 1e-8f);
    }
    __syncthreads();
    g_v1[t] = make_float2(a1 * fn1, b1 * fn1);
    g_v2[t] = make_float2(a2 * fn2, b2 * fn2);

    int r8 = ((t & 7) << 6) | (t & 56) | (t >> 6);
    float s, c;
    sincosf(angles[t], &s, &c);          g_d1r8[r8] = make_float2(c, s);
    sincosf(angles[512 + t], &s, &c);    g_d2r8[r8] = make_float2(c, s);
    sincosf(angles[1024 + t], &s, &c);   g_d3[t]    = make_float2(c, s);
    g_pp8[r8] = PAD(perm[t]);

    if (t < 64) {
        double ang = -2.0 * 3.14159265358979323846 * (double)t / 512.0;
        g_tw[t] = make_float2((float)cos(ang), (float)sin(ang));
    }
}

// ---------------- split-bf16 conversion --------------------------------------
__global__ void convert_x_kernel(const float* __restrict__ x) {
    int idx = blockIdx.x * 256 + threadIdx.x;
    float v = x[idx];
    __nv_bfloat16 hi = __float2bfloat16(v);
    __nv_bfloat16 lo = __float2bfloat16(v - __bfloat162float(hi));
    int row = idx >> 8, col = idx & 255;
    size_t b = (size_t)row * KCAT + col;
    g_xcat[b]       = hi;
    g_xcat[b + 256] = hi;
    g_xcat[b + 512] = lo;
}

__global__ void convert_w_kernel(const float* __restrict__ Wre,
                                 const float* __restrict__ Wim) {
    int idx = blockIdx.x * 256 + threadIdx.x;
    int h = idx >> 8, col = idx & 255;
    float v = (h < 512) ? Wre[(size_t)h * 256 + col]
                        : Wim[(size_t)(h - 512) * 256 + col];
    __nv_bfloat16 hi = __float2bfloat16(v);
    __nv_bfloat16 lo = __float2bfloat16(v - __bfloat162float(hi));
    size_t b = (size_t)h * KCAT + col;
    g_wcat[b]       = hi;
    g_wcat[b + 256] = lo;
    g_wcat[b + 512] = hi;
}

// ---------------- tensor-core GEMM: 4 warps, warp tile 64x64, cp.async x3 ----
#define STG  10240              // one 128x32 bf16 tile, 80B-padded rows
#define BOFF (3 * STG)          // B region offset in dynamic smem
#define NIT  (KCAT / 32)        // 24

__device__ __forceinline__ void ldsm_x4(u32 addr, u32& r0, u32& r1,
                                        u32& r2, u32& r3) {
    asm volatile("ldmatrix.sync.aligned.m8n8.x4.shared.b16 {%0,%1,%2,%3}, [%4];"
                 : "=r"(r0), "=r"(r1), "=r"(r2), "=r"(r3) : "r"(addr));
}
__device__ __forceinline__ void mma16816(float* c, const u32* a,
                                         u32 b0, u32 b1) {
    asm volatile(
        "mma.sync.aligned.m16n8k16.row.col.f32.bf16.bf16.f32 "
        "{%0,%1,%2,%3}, {%4,%5,%6,%7}, {%8,%9}, {%0,%1,%2,%3};"
        : "+f"(c[0]), "+f"(c[1]), "+f"(c[2]), "+f"(c[3])
        : "r"(a[0]), "r"(a[1]), "r"(a[2]), "r"(a[3]), "r"(b0), "r"(b1));
}

__global__ void __launch_bounds__(128) mma_gemm_kernel() {
    extern __shared__ __align__(16) char dsm[];

    int tid  = threadIdx.x;
    int warp = tid >> 5, lane = tid & 31;
    int bm = blockIdx.y << 7, bn = blockIdx.x << 7;
    int wm = (warp & 1) << 6, wn = (warp >> 1) << 6;

    u32 sBase = (u32)__cvta_generic_to_shared(dsm);

    // cp.async mapping: thread -> rows (tid>>2)+{0,32,64,96}, 16B at col (tid&3)*8
    int lr = tid >> 2, lc = (tid & 3) << 3;
    const __nv_bfloat16* gA = g_xcat + (size_t)(bm + lr) * KCAT + lc;
    const __nv_bfloat16* gB = g_wcat + (size_t)(bn + lr) * KCAT + lc;
    u32 stA = sBase + (u32)(lr * 80 + (tid & 3) * 16);
    u32 stB = stA + BOFF;

    // ldmatrix lane addressing
    int frow  = lane & 15;
    int fbyte = (lane >> 4) << 4;
    u32 aOff[4], bOff[4];
    #pragma unroll
    for (int i = 0; i < 4; i++)
        aOff[i] = (u32)((wm + i * 16 + frow) * 80 + fbyte);
    #pragma unroll
    for (int j = 0; j < 4; j++)
        bOff[j] = (u32)(BOFF + (wn + j * 16 + frow) * 80 + fbyte);

    float c[4][8][4];
    #pragma unroll
    for (int i = 0; i < 4; i++)
        #pragma unroll
        for (int o = 0; o < 8; o++)
            #pragma unroll
            for (int k = 0; k < 4; k++) c[i][o][k] = 0.f;

    // prologue: stages 0 and 1
    #pragma unroll
    for (int st = 0; st < 2; st++) {
        u32 offs = st * STG;
        int k = st * 32;
        #pragma unroll
        for (int p = 0; p < 4; p++) {
            asm volatile("cp.async.cg.shared.global [%0], [%1], 16;" ::
                "r"(stA + offs + p * 32 * 80), "l"(gA + (size_t)p * 32 * KCAT + k));
            asm volatile("cp.async.cg.shared.global [%0], [%1], 16;" ::
                "r"(stB + offs + p * 32 * 80), "l"(gB + (size_t)p * 32 * KCAT + k));
        }
        asm volatile("cp.async.commit_group;");
    }

    #pragma unroll 1
    for (int it = 0; it < NIT; it++) {
        asm volatile("cp.async.wait_group 1;");
        __syncthreads();
        // prefetch iter it+2 into stage (it+2)%3 (== stage read at it-1, safe past barrier)
        if (it + 2 < NIT) {
            int st = (it + 2) % 3;
            u32 offs = (u32)(st * STG);
            int k = (it + 2) * 32;
            #pragma unroll
            for (int p = 0; p < 4; p++) {
                asm volatile("cp.async.cg.shared.global [%0], [%1], 16;" ::
                    "r"(stA + offs + p * 32 * 80), "l"(gA + (size_t)p * 32 * KCAT + k));
                asm volatile("cp.async.cg.shared.global [%0], [%1], 16;" ::
                    "r"(stB + offs + p * 32 * 80), "l"(gB + (size_t)p * 32 * KCAT + k));
            }
        }
        asm volatile("cp.async.commit_group;");

        u32 so = sBase + (u32)((it % 3) * STG);
        #pragma unroll
        for (int kk = 0; kk < 2; kk++) {
            u32 a[4][4], b[4][4];
            #pragma unroll
            for (int i = 0; i < 4; i++)
                ldsm_x4(so + aOff[i] + kk * 32, a[i][0], a[i][1], a[i][2], a[i][3]);
            #pragma unroll
            for (int j = 0; j < 4; j++)
                ldsm_x4(so + bOff[j] + kk * 32, b[j][0], b[j][1], b[j][2], b[j][3]);
            // b[j][0]=n(16j..+7),k0-7  b[j][1]=n(16j+8..+15),k0-7
            // b[j][2]=n(16j..+7),k8-15 b[j][3]=n(16j+8..+15),k8-15
            #pragma unroll
            for (int i = 0; i < 4; i++)
                #pragma unroll
                for (int o = 0; o < 8; o++) {
                    int t = o >> 1, p = o & 1;
                    mma16816(c[i][o], a[i], b[t][p], b[t][p + 2]);
                }
        }
    }

    // epilogue
    int g = lane >> 2, tg = lane & 3;
    #pragma unroll
    for (int i = 0; i < 4; i++) {
        int r0 = bm + wm + i * 16 + g;
        #pragma unroll
        for (int o = 0; o < 8; o++) {
            int cc = bn + wn + o * 8 + tg * 2;
            *(float2*)(g_embP + (size_t)r0 * NCAT + cc)       = make_float2(c[i][o][0], c[i][o][1]);
            *(float2*)(g_embP + (size_t)(r0 + 8) * NCAT + cc) = make_float2(c[i][o][2], c[i][o][3]);
        }
    }
}

// ---------------- main per-row pipeline: 4 rows/block, radix-8 FFT -----------
__global__ void __launch_bounds__(256) urnn_kernel(const float* __restrict__ hxr,
                                                   const float* __restrict__ hxi,
                                                   const float* __restrict__ beta,
                                                   float2* __restrict__ out) {
    __shared__ float2 buf[4][576];
    __shared__ float2 sred[8];

    int tid = threadIdx.x;
    int sub = tid >> 6;
    int t   = tid & 63;
    int warp = tid >> 5;
    int row = (blockIdx.x << 2) + sub;
    size_t base  = (size_t)row * HID;
    size_t gbase = (size_t)(blockIdx.x << 2) * HID;

    #pragma unroll
    for (int n = 0; n < 8; n++) {
        int l = tid + (n << 8);
        int r = l >> 9, i = l & 511;
        buf[r][PAD(i)] = make_float2(hxr[gbase + l], hxi[gbase + l]);
    }
    __syncthreads();

    float2* b = buf[sub];
    float2 x[8];

    // ===== forward FFT =====
    #pragma unroll
    for (int k = 0; k < 8; k++) {
        int i  = (t << 3) + k;
        int r8 = (k << 6) + ((t & 7) << 3) + (t >> 3);
        x[k] = cmul(g_d1r8[i], b[PAD(r8)]);
    }
    dft8<-1>(x);
    __syncthreads();
    #pragma unroll
    for (int k = 0; k < 8; k++) b[PAD((t << 3) + k)] = x[k];
    __syncthreads();

    fft_stage1<-1>(b, t);
    __syncthreads();

    #pragma unroll
    for (int k = 0; k < 8; k++) x[k] = b[PAD(t + (k << 6))];
    {
        float2 w1 = g_tw[t];
        float2 w = w1;
        #pragma unroll
        for (int k = 1; k < 8; k++) { x[k] = cmul(x[k], w); w = cmul(w, w1); }
    }
    dft8<-1>(x);

    // Householder 1
    float2 v[8];
    float2 acc = make_float2(0.f, 0.f);
    #pragma unroll
    for (int k = 0; k < 8; k++) {
        v[k] = g_v1[t + (k << 6)];
        acc = cadd(acc, cmul(x[k], v[k]));
    }
    #pragma unroll
    for (int o = 16; o; o >>= 1) {
        acc.x += __shfl_xor_sync(0xffffffffu, acc.x, o);
        acc.y += __shfl_xor_sync(0xffffffffu, acc.y, o);
    }
    if ((tid & 31) == 0) sred[warp] = acc;
    __syncthreads();
    {
        float2 s = cadd(sred[sub << 1], sred[(sub << 1) | 1]);
        float2 m = make_float2(2.f * s.x, 2.f * s.y);
        #pragma unroll
        for (int k = 0; k < 8; k++)
            x[k] = csub(x[k], cmul(m, make_float2(v[k].x, -v[k].y)));
    }
    __syncthreads();
    #pragma unroll
    for (int k = 0; k < 8; k++) b[PAD(t + (k << 6))] = x[k];
    __syncthreads();

    // ===== inverse FFT =====
    #pragma unroll
    for (int k = 0; k < 8; k++) {
        int i = (t << 3) + k;
        x[k] = cmul(g_d2r8[i], b[g_pp8[i]]);
    }
    dft8<1>(x);
    __syncthreads();
    #pragma unroll
    for (int k = 0; k < 8; k++) b[PAD((t << 3) + k)] = x[k];
    __syncthreads();

    fft_stage1<1>(b, t);
    __syncthreads();

    #pragma unroll
    for (int k = 0; k < 8; k++) x[k] = b[PAD(t + (k << 6))];
    {
        float2 w1 = g_tw[t]; w1.y = -w1.y;
        float2 w = w1;
        #pragma unroll
        for (int k = 1; k < 8; k++) { x[k] = cmul(x[k], w); w = cmul(w, w1); }
    }
    dft8<1>(x);

    const float inv = 1.f / 512.f;
    #pragma unroll
    for (int k = 0; k < 8; k++) { x[k].x *= inv; x[k].y *= inv; }

    // Householder 2
    acc = make_float2(0.f, 0.f);
    #pragma unroll
    for (int k = 0; k < 8; k++) {
        v[k] = g_v2[t + (k << 6)];
        acc = cadd(acc, cmul(x[k], v[k]));
    }
    #pragma unroll
    for (int o = 16; o; o >>= 1) {
        acc.x += __shfl_xor_sync(0xffffffffu, acc.x, o);
        acc.y += __shfl_xor_sync(0xffffffffu, acc.y, o);
    }
    if ((tid & 31) == 0) sred[warp] = acc;
    __syncthreads();
    float2 s2 = cadd(sred[sub << 1], sred[(sub << 1) | 1]);
    float2 m2 = make_float2(2.f * s2.x, 2.f * s2.y);

    const float* embRe = g_embP + (size_t)row * NCAT;
    const float* embIm = embRe + 512;

    #pragma unroll
    for (int k = 0; k < 8; k++) {
        int e = t + (k << 6);
        float2 h = csub(x[k], cmul(m2, make_float2(v[k].x, -v[k].y)));
        h = cmul(g_d3[e], h);
        h.x += embRe[e]; h.y += embIm[e];
        float mag = sqrtf(h.x * h.x + h.y * h.y);
        float r = mag + beta[e];
        r = r > 0.f ? r : 0.f;
        float2 res;
        if (mag > 0.f) {
            float sc = r / mag;
            res = make_float2(sc * h.x, sc * h.y);
        } else {
            res = make_float2(r, 0.f);
        }
        out[base + e] = res;
    }
}

// ---------------- launch -----------------------------------------------------
extern "C" void kernel_launch(void* const* d_in, const int* in_sizes, int n_in,
                              void* d_out, int out_size) {
    const float* x      = (const float*)d_in[0];
    const float* hxr    = (const float*)d_in[1];
    const float* hxi    = (const float*)d_in[2];
    const float* angles = (const float*)d_in[3];
    const float* rre    = (const float*)d_in[4];
    const float* rim    = (const float*)d_in[5];
    const float* Wre    = (const float*)d_in[6];
    const float* Wim    = (const float*)d_in[7];
    const float* beta   = (const float*)d_in[8];
    const int*   perm   = (const int*)d_in[9];
    float2* out = (float2*)d_out;

    static int smem_set = 0;
    if (!smem_set) {
        cudaFuncSetAttribute(mma_gemm_kernel,
                             cudaFuncAttributeMaxDynamicSharedMemorySize, 6 * STG);
        smem_set = 1;
    }

    prep_kernel<<<1, 512>>>(angles, rre, rim, perm);
    convert_x_kernel<<<B_ROWS * IN / 256, 256>>>(x);
    convert_w_kernel<<<NCAT * IN / 256, 256>>>(Wre, Wim);
    dim3 gg(NCAT / 128, B_ROWS / 128);
    mma_gemm_kernel<<<gg, 128, 6 * STG>>>();
    urnn_kernel<<<B_ROWS / 4, 256>>>(hxr, hxi, beta, out);
}